// round 1
// baseline (speedup 1.0000x reference)
#include <cuda_runtime.h>

#define N_NODES 500000
#define N_EDGES 16000000
#define OUT_DIM 112

// Scratch (device globals — no allocation allowed in kernel_launch)
__device__ float  g_deg[N_NODES];            // degree, then overwritten with dinv
__device__ float4 g_t[N_NODES];              // pre-scaled transformed features t~ (dim<=4)
__device__ float4 g_agg[N_NODES];            // scatter accumulator

__device__ __forceinline__ void red_add_v4(float4* addr, float4 v) {
    asm volatile("red.global.add.v4.f32 [%0], {%1, %2, %3, %4};"
                 :: "l"(addr), "f"(v.x), "f"(v.y), "f"(v.z), "f"(v.w) : "memory");
}
__device__ __forceinline__ void red_add_v2(float2* addr, float2 v) {
    asm volatile("red.global.add.v2.f32 [%0], {%1, %2};"
                 :: "l"(addr), "f"(v.x), "f"(v.y) : "memory");
}

// ---------------------------------------------------------------------------
// deg init: deg[i] = 1 (self loop)
__global__ void k_init_deg() {
    int i = blockIdx.x * blockDim.x + threadIdx.x;
    if (i < N_NODES) g_deg[i] = 1.0f;
}

// deg accumulate: deg[dst] += 1 over all edges (vectorized index load)
__global__ void k_deg(const int4* __restrict__ dst4) {
    int i = blockIdx.x * blockDim.x + threadIdx.x;
    if (i < N_EDGES / 4) {
        int4 d = dst4[i];
        atomicAdd(&g_deg[d.x], 1.0f);
        atomicAdd(&g_deg[d.y], 1.0f);
        atomicAdd(&g_deg[d.z], 1.0f);
        atomicAdd(&g_deg[d.w], 1.0f);
    }
}

// ---------------------------------------------------------------------------
// Layer-1 transform: dinv = rsqrt(deg); t~ = dinv * (x @ W1^T); agg = 0
__global__ void k_l1(const float* __restrict__ x, const float* __restrict__ W1) {
    __shared__ float sW[32];                    // W1 is [4,8]
    if (threadIdx.x < 32) sW[threadIdx.x] = W1[threadIdx.x];
    __syncthreads();
    int i = blockIdx.x * blockDim.x + threadIdx.x;
    if (i >= N_NODES) return;
    float dinv = rsqrtf(g_deg[i]);
    g_deg[i] = dinv;                            // overwrite with dinv
    const float4* x4 = (const float4*)x;
    float4 xa = x4[2 * i], xb = x4[2 * i + 1];
    float t[4];
#pragma unroll
    for (int o = 0; o < 4; o++) {
        const float* w = sW + 8 * o;
        t[o] = w[0]*xa.x + w[1]*xa.y + w[2]*xa.z + w[3]*xa.w
             + w[4]*xb.x + w[5]*xb.y + w[6]*xb.z + w[7]*xb.w;
    }
    g_t[i]   = make_float4(dinv*t[0], dinv*t[1], dinv*t[2], dinv*t[3]);
    g_agg[i] = make_float4(0.f, 0.f, 0.f, 0.f);
}

// Edge scatter, 4-wide features: agg[dst] += t~[src]
__global__ void k_edge4(const int4* __restrict__ s4, const int4* __restrict__ d4) {
    int i = blockIdx.x * blockDim.x + threadIdx.x;
    if (i >= N_EDGES / 4) return;
    int4 s = s4[i], d = d4[i];
    red_add_v4(&g_agg[d.x], __ldg(&g_t[s.x]));
    red_add_v4(&g_agg[d.y], __ldg(&g_t[s.y]));
    red_add_v4(&g_agg[d.z], __ldg(&g_t[s.z]));
    red_add_v4(&g_agg[d.w], __ldg(&g_t[s.w]));
}

// Edge scatter, 2-wide features
__global__ void k_edge2(const int4* __restrict__ s4, const int4* __restrict__ d4) {
    int i = blockIdx.x * blockDim.x + threadIdx.x;
    if (i >= N_EDGES / 4) return;
    int4 s = s4[i], d = d4[i];
    const float2* t2 = (const float2*)g_t;
    float2* a2 = (float2*)g_agg;
    red_add_v2(&a2[d.x], __ldg(&t2[s.x]));
    red_add_v2(&a2[d.y], __ldg(&t2[s.y]));
    red_add_v2(&a2[d.z], __ldg(&t2[s.z]));
    red_add_v2(&a2[d.w], __ldg(&t2[s.w]));
}

// Epilogue(relu, b1) + transform W2 [4,4]: 4 -> 4
__global__ void k_l2(const float* __restrict__ W2, const float* __restrict__ b1) {
    __shared__ float sW[16], sb[4];
    if (threadIdx.x < 16) sW[threadIdx.x] = W2[threadIdx.x];
    if (threadIdx.x < 4)  sb[threadIdx.x] = b1[threadIdx.x];
    __syncthreads();
    int i = blockIdx.x * blockDim.x + threadIdx.x;
    if (i >= N_NODES) return;
    float dinv = g_deg[i];
    float4 a = g_agg[i], tt = g_t[i];
    float h[4];
    h[0] = fmaxf(dinv * (a.x + tt.x) + sb[0], 0.f);
    h[1] = fmaxf(dinv * (a.y + tt.y) + sb[1], 0.f);
    h[2] = fmaxf(dinv * (a.z + tt.z) + sb[2], 0.f);
    h[3] = fmaxf(dinv * (a.w + tt.w) + sb[3], 0.f);
    float t[4];
#pragma unroll
    for (int o = 0; o < 4; o++) {
        const float* w = sW + 4 * o;
        t[o] = w[0]*h[0] + w[1]*h[1] + w[2]*h[2] + w[3]*h[3];
    }
    g_t[i]   = make_float4(dinv*t[0], dinv*t[1], dinv*t[2], dinv*t[3]);
    g_agg[i] = make_float4(0.f, 0.f, 0.f, 0.f);
}

// Epilogue(tanh, b2) + transform W3 [2,4]: 4 -> 2
__global__ void k_l3(const float* __restrict__ W3, const float* __restrict__ b2) {
    __shared__ float sW[8], sb[4];
    if (threadIdx.x < 8) sW[threadIdx.x] = W3[threadIdx.x];
    if (threadIdx.x < 4) sb[threadIdx.x] = b2[threadIdx.x];
    __syncthreads();
    int i = blockIdx.x * blockDim.x + threadIdx.x;
    if (i >= N_NODES) return;
    float dinv = g_deg[i];
    float4 a = g_agg[i], tt = g_t[i];
    float h[4];
    h[0] = tanhf(dinv * (a.x + tt.x) + sb[0]);
    h[1] = tanhf(dinv * (a.y + tt.y) + sb[1]);
    h[2] = tanhf(dinv * (a.z + tt.z) + sb[2]);
    h[3] = tanhf(dinv * (a.w + tt.w) + sb[3]);
    float t0 = sW[0]*h[0] + sW[1]*h[1] + sW[2]*h[2] + sW[3]*h[3];
    float t1 = sW[4]*h[0] + sW[5]*h[1] + sW[6]*h[2] + sW[7]*h[3];
    ((float2*)g_t)[i]   = make_float2(dinv*t0, dinv*t1);
    ((float2*)g_agg)[i] = make_float2(0.f, 0.f);
}

// Epilogue(relu, b3) + transform W4 [2,2]: 2 -> 2
__global__ void k_l4(const float* __restrict__ W4, const float* __restrict__ b3) {
    __shared__ float sW[4], sb[2];
    if (threadIdx.x < 4) sW[threadIdx.x] = W4[threadIdx.x];
    if (threadIdx.x < 2) sb[threadIdx.x] = b3[threadIdx.x];
    __syncthreads();
    int i = blockIdx.x * blockDim.x + threadIdx.x;
    if (i >= N_NODES) return;
    float dinv = g_deg[i];
    float2 a = ((float2*)g_agg)[i], tt = ((float2*)g_t)[i];
    float h0 = fmaxf(dinv * (a.x + tt.x) + sb[0], 0.f);
    float h1 = fmaxf(dinv * (a.y + tt.y) + sb[1], 0.f);
    float t0 = sW[0]*h0 + sW[1]*h1;
    float t1 = sW[2]*h0 + sW[3]*h1;
    ((float2*)g_t)[i]   = make_float2(dinv*t0, dinv*t1);
    ((float2*)g_agg)[i] = make_float2(0.f, 0.f);
}

// Final epilogue(tanh, b4): h4 written directly to the tail of d_out
__global__ void k_l5(const float* __restrict__ b4, float* __restrict__ hout) {
    __shared__ float sb[2];
    if (threadIdx.x < 2) sb[threadIdx.x] = b4[threadIdx.x];
    __syncthreads();
    int i = blockIdx.x * blockDim.x + threadIdx.x;
    if (i >= N_NODES) return;
    float dinv = g_deg[i];
    float2 a = ((float2*)g_agg)[i], tt = ((float2*)g_t)[i];
    float h0 = tanhf(dinv * (a.x + tt.x) + sb[0]);
    float h1 = tanhf(dinv * (a.y + tt.y) + sb[1]);
    ((float2*)hout)[i] = make_float2(h0, h1);
}

// Classifier: out[n,k] = Wc[k,0]*h0 + Wc[k,1]*h1 + bc[k]
__global__ void k_cls(const float* __restrict__ Wc, const float* __restrict__ bc,
                      float* __restrict__ out, const float* __restrict__ h4) {
    __shared__ float sW[2 * OUT_DIM], sb[OUT_DIM];
    for (int j = threadIdx.x; j < 2 * OUT_DIM; j += blockDim.x) sW[j] = Wc[j];
    for (int j = threadIdx.x; j < OUT_DIM; j += blockDim.x)     sb[j] = bc[j];
    __syncthreads();
    long long idx = (long long)blockIdx.x * blockDim.x + threadIdx.x;
    if (idx >= (long long)N_NODES * OUT_DIM) return;
    int n = (int)(idx / OUT_DIM);
    int k = (int)(idx - (long long)n * OUT_DIM);
    float2 h = __ldg((const float2*)h4 + n);
    out[idx] = sW[2 * k] * h.x + sW[2 * k + 1] * h.y + sb[k];
}

// ---------------------------------------------------------------------------
extern "C" void kernel_launch(void* const* d_in, const int* in_sizes, int n_in,
                              void* d_out, int out_size) {
    const float* x   = (const float*)d_in[0];
    const int*   ei  = (const int*)d_in[1];       // [2, E]
    const float* W1  = (const float*)d_in[2];
    const float* b1  = (const float*)d_in[3];
    const float* W2  = (const float*)d_in[4];
    const float* b2  = (const float*)d_in[5];
    const float* W3  = (const float*)d_in[6];
    const float* b3  = (const float*)d_in[7];
    const float* W4  = (const float*)d_in[8];
    const float* b4  = (const float*)d_in[9];
    const float* Wc  = (const float*)d_in[10];
    const float* bc  = (const float*)d_in[11];

    const int4* src4 = (const int4*)ei;
    const int4* dst4 = (const int4*)(ei + N_EDGES);

    float* out  = (float*)d_out;                         // [N, 112]
    float* hout = out + (long long)N_NODES * OUT_DIM;    // [N, 2] tail

    const int TB = 256;
    const int nodeBlocks = (N_NODES + TB - 1) / TB;
    const int edgeBlocks = (N_EDGES / 4 + TB - 1) / TB;

    k_init_deg<<<nodeBlocks, TB>>>();
    k_deg<<<edgeBlocks, TB>>>(dst4);

    k_l1<<<nodeBlocks, TB>>>(x, W1);
    k_edge4<<<edgeBlocks, TB>>>(src4, dst4);

    k_l2<<<nodeBlocks, TB>>>(W2, b1);
    k_edge4<<<edgeBlocks, TB>>>(src4, dst4);

    k_l3<<<nodeBlocks, TB>>>(W3, b2);
    k_edge2<<<edgeBlocks, TB>>>(src4, dst4);

    k_l4<<<nodeBlocks, TB>>>(W4, b3);
    k_edge2<<<edgeBlocks, TB>>>(src4, dst4);

    k_l5<<<nodeBlocks, TB>>>(b4, hout);

    long long total = (long long)N_NODES * OUT_DIM;
    int clsBlocks = (int)((total + TB - 1) / TB);
    k_cls<<<clsBlocks, TB>>>(Wc, bc, out, hout);
}

// round 3
// speedup vs baseline: 1.4713x; 1.4713x over previous
#include <cuda_runtime.h>

#define N_NODES 500000
#define N_EDGES 16000000
#define OUT_DIM 112
#define SCAN_TILE 2048
#define NB_SCAN ((N_NODES + SCAN_TILE - 1) / SCAN_TILE)   // 245

// ---- device scratch (static globals; referenced ONLY in device code) ----
__device__ int    g_cnt[N_NODES];
__device__ int    g_rowptr[N_NODES + 1];
__device__ int    g_cur[N_NODES];
__device__ int    g_bsum[NB_SCAN];
__device__ int    g_csrc[N_EDGES];        // CSR column (src) indices, grouped by dst
__device__ float  g_dinv[N_NODES];
__device__ float4 g_ta[N_NODES];          // ping
__device__ float4 g_tb[N_NODES];          // pong

// ---------------------------------------------------------------------------
__global__ void k_zero() {
    int i = blockIdx.x * blockDim.x + threadIdx.x;
    if (i < N_NODES) g_cnt[i] = 0;
}

__global__ void k_hist(const int4* __restrict__ d4) {
    int i = blockIdx.x * blockDim.x + threadIdx.x;
    if (i >= N_EDGES / 4) return;
    int4 d = d4[i];
    atomicAdd(&g_cnt[d.x], 1);
    atomicAdd(&g_cnt[d.y], 1);
    atomicAdd(&g_cnt[d.z], 1);
    atomicAdd(&g_cnt[d.w], 1);
}

// Block-local exclusive scan of g_cnt (2048 elems/block); block totals -> g_bsum
__global__ void k_scan1() {
    __shared__ int sh[256];
    int tid = threadIdx.x;
    int base = blockIdx.x * SCAN_TILE + tid * 8;
    int v[8];
    int s = 0;
#pragma unroll
    for (int j = 0; j < 8; j++) {
        int idx = base + j;
        v[j] = (idx < N_NODES) ? g_cnt[idx] : 0;
        s += v[j];
    }
    sh[tid] = s;
    __syncthreads();
    for (int o = 1; o < 256; o <<= 1) {
        int t = (tid >= o) ? sh[tid - o] : 0;
        __syncthreads();
        sh[tid] += t;
        __syncthreads();
    }
    int incl = sh[tid];
    if (tid == 255) g_bsum[blockIdx.x] = incl;
    int run = incl - s;   // thread-exclusive prefix
#pragma unroll
    for (int j = 0; j < 8; j++) {
        int idx = base + j;
        if (idx < N_NODES) g_rowptr[idx] = run;
        run += v[j];
    }
}

// Exclusive scan of the 245 block sums (single block)
__global__ void k_scan2() {
    __shared__ int sh[256];
    int tid = threadIdx.x;
    int v = (tid < NB_SCAN) ? g_bsum[tid] : 0;
    sh[tid] = v;
    __syncthreads();
    for (int o = 1; o < 256; o <<= 1) {
        int t = (tid >= o) ? sh[tid - o] : 0;
        __syncthreads();
        sh[tid] += t;
        __syncthreads();
    }
    if (tid < NB_SCAN) g_bsum[tid] = sh[tid] - v;
}

// Add block offsets; init fill cursors; write sentinel
__global__ void k_scan3() {
    int i = blockIdx.x * blockDim.x + threadIdx.x;
    if (i < N_NODES) {
        int v = g_rowptr[i] + g_bsum[i / SCAN_TILE];
        g_rowptr[i] = v;
        g_cur[i] = v;
    }
    if (i == 0) g_rowptr[N_NODES] = N_EDGES;
}

// Fill CSR: for each edge, place src into dst's slot
__global__ void k_fill(const int4* __restrict__ s4, const int4* __restrict__ d4) {
    int i = blockIdx.x * blockDim.x + threadIdx.x;
    if (i >= N_EDGES / 4) return;
    int4 s = s4[i], d = d4[i];
    g_csrc[atomicAdd(&g_cur[d.x], 1)] = s.x;
    g_csrc[atomicAdd(&g_cur[d.y], 1)] = s.y;
    g_csrc[atomicAdd(&g_cur[d.z], 1)] = s.z;
    g_csrc[atomicAdd(&g_cur[d.w], 1)] = s.w;
}

// Layer-1 node transform: dinv = rsqrt(deg); t~ = dinv * (x @ W1^T)
__global__ void k_l1(const float* __restrict__ x, const float* __restrict__ W1) {
    __shared__ float sW[32];                    // W1 is [4,8]
    if (threadIdx.x < 32) sW[threadIdx.x] = W1[threadIdx.x];
    __syncthreads();
    int i = blockIdx.x * blockDim.x + threadIdx.x;
    if (i >= N_NODES) return;
    float dinv = rsqrtf((float)g_cnt[i] + 1.0f);
    g_dinv[i] = dinv;
    const float4* x4 = (const float4*)x;
    float4 xa = x4[2 * i], xb = x4[2 * i + 1];
    float t[4];
#pragma unroll
    for (int o = 0; o < 4; o++) {
        const float* w = sW + 8 * o;
        t[o] = w[0]*xa.x + w[1]*xa.y + w[2]*xa.z + w[3]*xa.w
             + w[4]*xb.x + w[5]*xb.y + w[6]*xb.z + w[7]*xb.w;
    }
    g_ta[i] = make_float4(dinv*t[0], dinv*t[1], dinv*t[2], dinv*t[3]);
}

// Fused gather + epilogue + next transform. One warp per node.
// SRC_A: read from g_ta (else g_tb); non-FINAL writes the opposite buffer.
// h = act(dinv*(sum_{src} t~[src] + t~[i]) + b);  t'_out = dinv*(h @ W^T)
template<int IN, int OUT, bool RELU, bool SRC_A, bool FINAL>
__global__ void k_conv(float* __restrict__ hout,
                       const float* __restrict__ W, const float* __restrict__ b) {
    const float* tin = SRC_A ? (const float*)g_ta : (const float*)g_tb;
    float* tout = FINAL ? hout : (SRC_A ? (float*)g_tb : (float*)g_ta);

    int gw = (blockIdx.x * blockDim.x + threadIdx.x) >> 5;
    int lane = threadIdx.x & 31;
    if (gw >= N_NODES) return;
    int start = g_rowptr[gw], end = g_rowptr[gw + 1];
    float acc[IN];
#pragma unroll
    for (int c = 0; c < IN; c++) acc[c] = 0.f;
    for (int e = start + lane; e < end; e += 32) {
        int s = __ldg(g_csrc + e);
        if (IN == 4) {
            float4 v = __ldg((const float4*)tin + s);
            acc[0] += v.x; acc[1] += v.y; acc[2] += v.z; acc[3] += v.w;
        } else {
            float2 v = __ldg((const float2*)tin + s);
            acc[0] += v.x; acc[1] += v.y;
        }
    }
#pragma unroll
    for (int o = 16; o; o >>= 1) {
#pragma unroll
        for (int c = 0; c < IN; c++)
            acc[c] += __shfl_xor_sync(0xffffffffu, acc[c], o);
    }
    if (lane == 0) {
        float dinv = g_dinv[gw];
        float h[IN];
        if (IN == 4) {
            float4 sv = __ldg((const float4*)tin + gw);
            float self[4] = {sv.x, sv.y, sv.z, sv.w};
#pragma unroll
            for (int c = 0; c < 4; c++) {
                float z = dinv * (acc[c] + self[c]) + __ldg(b + c);
                h[c] = RELU ? fmaxf(z, 0.f) : tanhf(z);
            }
        } else {
            float2 sv = __ldg((const float2*)tin + gw);
            float self[2] = {sv.x, sv.y};
#pragma unroll
            for (int c = 0; c < 2; c++) {
                float z = dinv * (acc[c] + self[c]) + __ldg(b + c);
                h[c] = RELU ? fmaxf(z, 0.f) : tanhf(z);
            }
        }
        if (FINAL) {
            ((float2*)tout)[gw] = make_float2(h[0], h[1]);
        } else {
            float t[OUT];
#pragma unroll
            for (int o = 0; o < OUT; o++) {
                float sum = 0.f;
#pragma unroll
                for (int c = 0; c < IN; c++) sum += __ldg(W + o * IN + c) * h[c];
                t[o] = dinv * sum;
            }
            if (OUT == 4)
                ((float4*)tout)[gw] = make_float4(t[0], t[1], t[2], t[3]);
            else
                ((float2*)tout)[gw] = make_float2(t[0], t[1]);
        }
    }
}

// Classifier: out[n,k] = Wc[k,0]*h0 + Wc[k,1]*h1 + bc[k], 4 outputs/thread
__global__ void k_cls(const float* __restrict__ Wc, const float* __restrict__ bc,
                      float4* __restrict__ out, const float* __restrict__ h4) {
    __shared__ float sW[2 * OUT_DIM], sb[OUT_DIM];
    for (int j = threadIdx.x; j < 2 * OUT_DIM; j += blockDim.x) sW[j] = Wc[j];
    for (int j = threadIdx.x; j < OUT_DIM; j += blockDim.x)     sb[j] = bc[j];
    __syncthreads();
    const long long TOTAL = (long long)N_NODES * (OUT_DIM / 4);
    long long idx = (long long)blockIdx.x * blockDim.x + threadIdx.x;
    if (idx >= TOTAL) return;
    int n  = (int)(idx / (OUT_DIM / 4));
    int kq = (int)(idx - (long long)n * (OUT_DIM / 4));
    float2 h = __ldg((const float2*)h4 + n);
    int k = kq * 4;
    float4 r;
    r.x = sW[2*(k+0)] * h.x + sW[2*(k+0)+1] * h.y + sb[k+0];
    r.y = sW[2*(k+1)] * h.x + sW[2*(k+1)+1] * h.y + sb[k+1];
    r.z = sW[2*(k+2)] * h.x + sW[2*(k+2)+1] * h.y + sb[k+2];
    r.w = sW[2*(k+3)] * h.x + sW[2*(k+3)+1] * h.y + sb[k+3];
    out[idx] = r;
}

// ---------------------------------------------------------------------------
extern "C" void kernel_launch(void* const* d_in, const int* in_sizes, int n_in,
                              void* d_out, int out_size) {
    const float* x   = (const float*)d_in[0];
    const int*   ei  = (const int*)d_in[1];       // [2, E]
    const float* W1  = (const float*)d_in[2];
    const float* b1  = (const float*)d_in[3];
    const float* W2  = (const float*)d_in[4];
    const float* b2  = (const float*)d_in[5];
    const float* W3  = (const float*)d_in[6];
    const float* b3  = (const float*)d_in[7];
    const float* W4  = (const float*)d_in[8];
    const float* b4  = (const float*)d_in[9];
    const float* Wc  = (const float*)d_in[10];
    const float* bc  = (const float*)d_in[11];

    const int4* src4 = (const int4*)ei;
    const int4* dst4 = (const int4*)(ei + N_EDGES);

    float* out  = (float*)d_out;                         // [N, 112]
    float* hout = out + (long long)N_NODES * OUT_DIM;    // [N, 2] tail

    const int TB = 256;
    const int nodeBlocks = (N_NODES + TB - 1) / TB;
    const int edgeBlocks = (N_EDGES / 4 + TB - 1) / TB;
    const int convBlocks = (N_NODES * 32 + TB - 1) / TB; // warp per node

    // CSR build
    k_zero <<<nodeBlocks, TB>>>();
    k_hist <<<edgeBlocks, TB>>>(dst4);
    k_scan1<<<NB_SCAN, 256>>>();
    k_scan2<<<1, 256>>>();
    k_scan3<<<nodeBlocks, TB>>>();
    k_fill <<<edgeBlocks, TB>>>(src4, dst4);

    // Layer pipeline (gather-fused):
    // l1 transform -> conv(b1,relu,W2) -> conv(b2,tanh,W3) -> conv(b3,relu,W4) -> conv(b4,tanh,FINAL)
    k_l1<<<nodeBlocks, TB>>>(x, W1);
    k_conv<4, 4, true,  true,  false><<<convBlocks, TB>>>(nullptr, W2, b1);
    k_conv<4, 2, false, false, false><<<convBlocks, TB>>>(nullptr, W3, b2);
    k_conv<2, 2, true,  true,  false><<<convBlocks, TB>>>(nullptr, W4, b3);
    k_conv<2, 2, false, false, true ><<<convBlocks, TB>>>(hout, W4, b4);

    const long long clsTotal = (long long)N_NODES * (OUT_DIM / 4);
    int clsBlocks = (int)((clsTotal + TB - 1) / TB);
    k_cls<<<clsBlocks, TB>>>(Wc, bc, (float4*)out, hout);
}